// round 3
// baseline (speedup 1.0000x reference)
#include <cuda_runtime.h>
#include <cstdint>

#define DEV_INLINE __device__ __forceinline__

// ---------------- problem constants ----------------
// B=2, TV=8192, TL=256, E=2048, H=8, D=256, VD=256, LD=768, scale=0.0625

// ---------------- scratch ----------------
__device__ __align__(16) float g_q   [(size_t)16 * 8192 * 256];   // [b,h,t,d]
__device__ __align__(16) float g_vv  [(size_t)16 * 8192 * 256];   // [b,h,t,d]
__device__ __align__(16) float g_k   [16 * 256 * 256];            // [b,h,s,d]
__device__ __align__(16) float g_vl  [16 * 256 * 256];            // [b,h,s,d] pre-masked
__device__ __align__(16) float g_W   [(size_t)16 * 8192 * 256];   // exp(clip(attn))
__device__ __align__(16) float g_outv1[(size_t)2 * 8192 * 2048];  // [b,t,E]
__device__ __align__(16) float g_outl1[2 * 256 * 2048];           // [b,s,E] (split-K acc)
__device__ float g_rowZ[16 * 8192];
__device__ float g_colZ[16 * 256];
__device__ float g_maskf[512];

// ---------------- helpers ----------------
DEV_INLINE uint32_t frag_cvt(const float* p) {
    uint32_t u;
    asm("cvt.rna.tf32.f32 %0, %1;" : "=r"(u) : "f"(*p));
    return u;
}

DEV_INLINE void mma8(float (&c)[4], const uint32_t (&a)[4], const uint32_t (&b)[2]) {
    asm volatile(
        "mma.sync.aligned.m16n8k8.row.col.f32.tf32.tf32.f32 "
        "{%0,%1,%2,%3}, {%4,%5,%6,%7}, {%8,%9}, {%0,%1,%2,%3};\n"
        : "+f"(c[0]), "+f"(c[1]), "+f"(c[2]), "+f"(c[3])
        : "r"(a[0]), "r"(a[1]), "r"(a[2]), "r"(a[3]), "r"(b[0]), "r"(b[1]));
}

DEV_INLINE void cp16(float* dst, const float* src) {
    uint32_t d = (uint32_t)__cvta_generic_to_shared(dst);
    asm volatile("cp.async.cg.shared.global [%0], [%1], 16;\n" :: "r"(d), "l"(src));
}
DEV_INLINE void cpcommit() { asm volatile("cp.async.commit_group;\n"); }
DEV_INLINE void cpwait1()  { asm volatile("cp.async.wait_group 1;\n"); }

// ---------------- GEMM core: BM=128, BN=128, BK=32, 256 thr, 2-stage cp.async ----------
// warps: 2 rows x 4 cols, each warp computes 64x32
// smem strides chosen conflict-free:
//  A normal [m][36], A trans [k][136], B KN [k][136], B NT [n][36]
constexpr int BM = 128, BN = 128, BK = 32;
constexpr int SMEM_BYTES = 2 * (128 * 36 + 128 * 36) * 4;   // 73728 (max config)

template<bool ATRANS, bool BNT>
DEV_INLINE void load_stage(const float* A, const float* B, int k0,
                           int lda, int ldb, int m0, int n0,
                           float* As, float* Bs, int tid) {
    if (!ATRANS) {
        #pragma unroll
        for (int i = 0; i < 4; i++) {
            int lin = tid + i * 256;
            int r = lin >> 3, c4 = (lin & 7) << 2;
            cp16(As + r * 36 + c4, A + (size_t)(m0 + r) * lda + k0 + c4);
        }
    } else {
        #pragma unroll
        for (int i = 0; i < 4; i++) {
            int lin = tid + i * 256;
            int kk = lin >> 5, m4 = (lin & 31) << 2;
            cp16(As + kk * 136 + m4, A + (size_t)(k0 + kk) * lda + m0 + m4);
        }
    }
    if (BNT) {
        #pragma unroll
        for (int i = 0; i < 4; i++) {
            int lin = tid + i * 256;
            int r = lin >> 3, c4 = (lin & 7) << 2;
            cp16(Bs + r * 36 + c4, B + (size_t)(n0 + r) * ldb + k0 + c4);
        }
    } else {
        #pragma unroll
        for (int i = 0; i < 4; i++) {
            int lin = tid + i * 256;
            int kk = lin >> 5, n4 = (lin & 31) << 2;
            cp16(Bs + kk * 136 + n4, B + (size_t)(k0 + kk) * ldb + n0 + n4);
        }
    }
}

template<bool ATRANS, bool BNT>
DEV_INLINE void compute_stage(const float* As, const float* Bs,
                              int wm, int wn, int gid, int tig,
                              float (&acc)[4][4][4]) {
    #pragma unroll
    for (int ks = 0; ks < 4; ks++) {
        const int kb = ks << 3;
        uint32_t a[4][4], b[4][2];
        #pragma unroll
        for (int im = 0; im < 4; im++) {
            int row = wm + im * 16 + gid;
            if (!ATRANS) {
                a[im][0] = frag_cvt(As + row * 36 + kb + tig);
                a[im][1] = frag_cvt(As + (row + 8) * 36 + kb + tig);
                a[im][2] = frag_cvt(As + row * 36 + kb + tig + 4);
                a[im][3] = frag_cvt(As + (row + 8) * 36 + kb + tig + 4);
            } else {
                a[im][0] = frag_cvt(As + (kb + tig) * 136 + row);
                a[im][1] = frag_cvt(As + (kb + tig) * 136 + row + 8);
                a[im][2] = frag_cvt(As + (kb + tig + 4) * 136 + row);
                a[im][3] = frag_cvt(As + (kb + tig + 4) * 136 + row + 8);
            }
        }
        #pragma unroll
        for (int jn = 0; jn < 4; jn++) {
            int col = wn + jn * 8 + gid;
            if (BNT) {
                b[jn][0] = frag_cvt(Bs + col * 36 + kb + tig);
                b[jn][1] = frag_cvt(Bs + col * 36 + kb + tig + 4);
            } else {
                b[jn][0] = frag_cvt(Bs + (kb + tig) * 136 + col);
                b[jn][1] = frag_cvt(Bs + (kb + tig + 4) * 136 + col);
            }
        }
        #pragma unroll
        for (int im = 0; im < 4; im++)
            #pragma unroll
            for (int jn = 0; jn < 4; jn++)
                mma8(acc[im][jn], a[im], b[jn]);
    }
}

template<bool ATRANS, bool BNT>
DEV_INLINE void gemm_core(const float* A, const float* B, int kbeg, int kcnt,
                          int lda, int ldb, int m0, int n0, float (&acc)[4][4][4]) {
    extern __shared__ float smem[];
    constexpr int ASZ = ATRANS ? 32 * 136 : 128 * 36;
    constexpr int BSZ = BNT ? 128 * 36 : 32 * 136;
    float* Asb[2] = { smem, smem + ASZ };
    float* Bsb[2] = { smem + 2 * ASZ, smem + 2 * ASZ + BSZ };

    const int tid = threadIdx.x;
    const int lane = tid & 31, warp = tid >> 5;
    const int wm = (warp >> 2) * 64, wn = (warp & 3) * 32;
    const int gid = lane >> 2, tig = lane & 3;

    #pragma unroll
    for (int i = 0; i < 4; i++)
        #pragma unroll
        for (int j = 0; j < 4; j++)
            #pragma unroll
            for (int q = 0; q < 4; q++) acc[i][j][q] = 0.f;

    const int nk = kcnt >> 5;
    load_stage<ATRANS, BNT>(A, B, kbeg, lda, ldb, m0, n0, Asb[0], Bsb[0], tid);
    cpcommit();
    for (int i = 0; i < nk; i++) {
        if (i + 1 < nk)
            load_stage<ATRANS, BNT>(A, B, kbeg + ((i + 1) << 5), lda, ldb, m0, n0,
                                    Asb[(i + 1) & 1], Bsb[(i + 1) & 1], tid);
        cpcommit();
        cpwait1();
        __syncthreads();
        compute_stage<ATRANS, BNT>(Asb[i & 1], Bsb[i & 1], wm, wn, gid, tig, acc);
        __syncthreads();
    }
}

// ---------------- generic GEMM kernel ----------------
struct GemmP {
    const float* A; const float* B;
    int K, lda, ldb;
    long aB, bB;
    int ksplit;
};

template<bool ATRANS, bool BNT, class Epi>
__global__ __launch_bounds__(256, 2) void gemm_kernel(GemmP p, Epi epi) {
    const int zz = blockIdx.z;
    const int z  = (p.ksplit > 1) ? zz / p.ksplit : zz;
    const int sp = (p.ksplit > 1) ? zz % p.ksplit : 0;
    const int kcnt = p.K / p.ksplit;
    const int kbeg = sp * kcnt;
    const float* A = p.A + (size_t)z * p.aB;
    const float* B = p.B + (size_t)z * p.bB;
    const int m0 = blockIdx.y * BM, n0 = blockIdx.x * BN;

    float acc[4][4][4];
    gemm_core<ATRANS, BNT>(A, B, kbeg, kcnt, p.lda, p.ldb, m0, n0, acc);

    const int lane = threadIdx.x & 31, warp = threadIdx.x >> 5;
    const int wm = (warp >> 2) * 64, wn = (warp & 3) * 32;
    const int gid = lane >> 2, tig = lane & 3;
    #pragma unroll
    for (int im = 0; im < 4; im++)
        #pragma unroll
        for (int jn = 0; jn < 4; jn++)
            #pragma unroll
            for (int qd = 0; qd < 4; qd++) {
                int r = m0 + wm + im * 16 + gid + ((qd >> 1) << 3);
                int c = n0 + wn + jn * 8 + tig * 2 + (qd & 1);
                epi(z, r, c, acc[im][jn][qd]);
            }
}

// ---------------- dual-projection kernel (shared A, z picks weights) ----------------
struct DualP {
    const float* A;
    const float* B0; const float* B1;
    const float* bias0; const float* bias1;
    const float* mask;          // applied when z==1 (vl)
    float* out0; float* out1;
    float a0, a1;
    int K, lda, ldb, T;
};

__global__ __launch_bounds__(256, 2) void dual_kernel(DualP p) {
    const int z = blockIdx.z;
    const float* B = z ? p.B1 : p.B0;
    const int m0 = blockIdx.y * BM, n0 = blockIdx.x * BN;

    float acc[4][4][4];
    gemm_core<false, false>(p.A, B, 0, p.K, p.lda, p.ldb, m0, n0, acc);

    const float* bias = z ? p.bias1 : p.bias0;
    float* out = z ? p.out1 : p.out0;
    const float alpha = z ? p.a1 : p.a0;
    const bool useMask = (p.mask != nullptr) && (z == 1);

    const int lane = threadIdx.x & 31, warp = threadIdx.x >> 5;
    const int wm = (warp >> 2) * 64, wn = (warp & 3) * 32;
    const int gid = lane >> 2, tig = lane & 3;
    #pragma unroll
    for (int im = 0; im < 4; im++)
        #pragma unroll
        for (int jn = 0; jn < 4; jn++)
            #pragma unroll
            for (int qd = 0; qd < 4; qd++) {
                int r = m0 + wm + im * 16 + gid + ((qd >> 1) << 3);
                int c = n0 + wn + jn * 8 + tig * 2 + (qd & 1);
                float x = (acc[im][jn][qd] + bias[c]) * alpha;
                if (useMask) x *= p.mask[r];
                int b = r / p.T, t = r - b * p.T;
                int h = c >> 8, d = c & 255;
                out[(((size_t)(b * 8 + h)) * p.T + t) * 256 + d] = x;
            }
}

// ---------------- epilogues ----------------
struct EpiOutV {
    const float* rowZ; float* out;
    DEV_INLINE void operator()(int z, int r, int c, float v) const {
        int b = z >> 3, h = z & 7;
        out[((size_t)b * 8192 + r) * 2048 + h * 256 + c] = v / rowZ[z * 8192 + r];
    }
};
struct EpiBias {
    const float* bias; float* out; int ldc;
    DEV_INLINE void operator()(int, int r, int c, float v) const {
        out[(size_t)r * ldc + c] = v + bias[c];
    }
};
struct EpiAtomL {
    float* out;
    DEV_INLINE void operator()(int z, int r, int c, float v) const {
        int b = z >> 3, h = z & 7;
        atomicAdd(&out[((size_t)b * 256 + r) * 2048 + h * 256 + c], v);
    }
};
struct EpiAtomPlain {
    float* out; int ldc;
    DEV_INLINE void operator()(int, int r, int c, float v) const {
        atomicAdd(&out[(size_t)r * ldc + c], v);
    }
};

// ---------------- attention kernel ----------------
__global__ __launch_bounds__(256, 2) void attn_kernel(
    const float* __restrict__ q, const float* __restrict__ kmat,
    float* __restrict__ W, const float* __restrict__ maskf,
    float* __restrict__ rowZ, float* __restrict__ colZ) {
    __shared__ float s_row[BM];
    __shared__ float s_col[BN];
    __shared__ float s_mask[BN];

    const int z = blockIdx.z;
    const float* A = q    + (size_t)z * (8192 * 256);
    const float* B = kmat + (size_t)z * (256 * 256);
    const int m0 = blockIdx.y * BM, n0 = blockIdx.x * BN;
    const int tid = threadIdx.x;

    if (tid < BM) s_row[tid] = 0.f;
    if (tid < BN) {
        s_col[tid] = 0.f;
        s_mask[tid] = maskf[(z >> 3) * 256 + n0 + tid];
    }
    // core's internal __syncthreads orders these before the epilogue

    float acc[4][4][4];
    gemm_core<false, true>(A, B, 0, 256, 256, 256, m0, n0, acc);

    const int lane = tid & 31, warp = tid >> 5;
    const int wm = (warp >> 2) * 64, wn = (warp & 3) * 32;
    const int gid = lane >> 2, tig = lane & 3;
    const size_t wbase = (size_t)z * (8192 * 256);

    float colp[4][2] = {};   // [jn][q&1]  (sum over this thread's 8 rows)
    float rowp[4][2] = {};   // [im][q>>1] (mask-weighted sum over 8 cols)

    #pragma unroll
    for (int im = 0; im < 4; im++)
        #pragma unroll
        for (int jn = 0; jn < 4; jn++)
            #pragma unroll
            for (int qd = 0; qd < 4; qd++) {
                int rr = wm + im * 16 + gid + ((qd >> 1) << 3);
                int cc = wn + jn * 8 + tig * 2 + (qd & 1);
                float x = fminf(fmaxf(acc[im][jn][qd], -50000.f), 50000.f);
                float w = __expf(x);
                W[wbase + (size_t)(m0 + rr) * 256 + (n0 + cc)] = w;
                colp[jn][qd & 1] += w;
                rowp[im][qd >> 1] += w * s_mask[cc];
            }

    // column sums: reduce across gid (lane bits 2..4); lane gid==0 commits
    #pragma unroll
    for (int jn = 0; jn < 4; jn++)
        #pragma unroll
        for (int q1 = 0; q1 < 2; q1++) {
            float v = colp[jn][q1];
            v += __shfl_xor_sync(0xffffffffu, v, 4);
            v += __shfl_xor_sync(0xffffffffu, v, 8);
            v += __shfl_xor_sync(0xffffffffu, v, 16);
            if (gid == 0) atomicAdd(&s_col[wn + jn * 8 + tig * 2 + q1], v);
        }
    // row sums: reduce across tig (lane bits 0..1); lane tig==0 commits
    #pragma unroll
    for (int im = 0; im < 4; im++)
        #pragma unroll
        for (int qh = 0; qh < 2; qh++) {
            float v = rowp[im][qh];
            v += __shfl_xor_sync(0xffffffffu, v, 1);
            v += __shfl_xor_sync(0xffffffffu, v, 2);
            if (tig == 0) atomicAdd(&s_row[wm + im * 16 + gid + qh * 8], v);
        }

    __syncthreads();
    if (tid < BM) atomicAdd(&rowZ[z * 8192 + m0 + tid], s_row[tid]);
    if (tid < BN) atomicAdd(&colZ[z * 256 + n0 + tid], s_col[tid]);
}

// ---------------- small kernels ----------------
__global__ void prep_kernel(const int* __restrict__ mask, float* __restrict__ outl_region) {
    int i = blockIdx.x * 256 + threadIdx.x;
    int n = gridDim.x * 256;
    for (int j = i; j < 2 * 256 * 2048; j += n) g_outl1[j] = 0.f;
    for (int j = i; j < 512 * 768;      j += n) outl_region[j] = 0.f;
    for (int j = i; j < 16 * 8192;      j += n) g_rowZ[j] = 0.f;
    for (int j = i; j < 16 * 256;       j += n) g_colZ[j] = 0.f;
    for (int j = i; j < 512;            j += n) g_maskf[j] = (float)mask[j];
}

__global__ void scale_outl1_kernel() {
    int i = blockIdx.x * 256 + threadIdx.x;   // total 2*256*2048 = 1048576
    int b = i / (256 * 2048);
    int rem = i - b * (256 * 2048);
    int s = rem >> 11;
    int h = (rem >> 8) & 7;
    g_outl1[i] = g_outl1[i] / g_colZ[(b * 8 + h) * 256 + s];
}

__global__ void add_bol_kernel(float* __restrict__ out, const float* __restrict__ bol) {
    int i = blockIdx.x * 256 + threadIdx.x;   // total 512*768 = 393216
    if (i < 512 * 768) out[i] += bol[i % 768];
}

// ---------------- host ----------------
extern "C" void kernel_launch(void* const* d_in, const int* in_sizes, int n_in,
                              void* d_out, int out_size) {
    (void)in_sizes; (void)n_in; (void)out_size;
    const float* v    = (const float*)d_in[0];
    const float* l    = (const float*)d_in[1];
    const int*   mask = (const int*)d_in[2];
    const float* Wv   = (const float*)d_in[3];
    const float* bv   = (const float*)d_in[4];
    const float* Wl   = (const float*)d_in[5];
    const float* bl   = (const float*)d_in[6];
    const float* Wvv  = (const float*)d_in[7];
    const float* bvv  = (const float*)d_in[8];
    const float* Wvl  = (const float*)d_in[9];
    const float* bvl  = (const float*)d_in[10];
    const float* Wov  = (const float*)d_in[11];
    const float* bov  = (const float*)d_in[12];
    const float* Wol  = (const float*)d_in[13];
    const float* bol  = (const float*)d_in[14];
    float* out = (float*)d_out;

    float *pq, *pvv, *pk, *pvl, *pW, *pov1, *pol1, *prz, *pcz, *pm;
    cudaGetSymbolAddress((void**)&pq,   g_q);
    cudaGetSymbolAddress((void**)&pvv,  g_vv);
    cudaGetSymbolAddress((void**)&pk,   g_k);
    cudaGetSymbolAddress((void**)&pvl,  g_vl);
    cudaGetSymbolAddress((void**)&pW,   g_W);
    cudaGetSymbolAddress((void**)&pov1, g_outv1);
    cudaGetSymbolAddress((void**)&pol1, g_outl1);
    cudaGetSymbolAddress((void**)&prz,  g_rowZ);
    cudaGetSymbolAddress((void**)&pcz,  g_colZ);
    cudaGetSymbolAddress((void**)&pm,   g_maskf);

    // opt-in dynamic smem
    cudaFuncSetAttribute(dual_kernel, cudaFuncAttributeMaxDynamicSharedMemorySize, SMEM_BYTES);
    cudaFuncSetAttribute(attn_kernel, cudaFuncAttributeMaxDynamicSharedMemorySize, SMEM_BYTES);
    cudaFuncSetAttribute(gemm_kernel<false, false, EpiOutV>,      cudaFuncAttributeMaxDynamicSharedMemorySize, SMEM_BYTES);
    cudaFuncSetAttribute(gemm_kernel<false, false, EpiBias>,      cudaFuncAttributeMaxDynamicSharedMemorySize, SMEM_BYTES);
    cudaFuncSetAttribute(gemm_kernel<true,  false, EpiAtomL>,     cudaFuncAttributeMaxDynamicSharedMemorySize, SMEM_BYTES);
    cudaFuncSetAttribute(gemm_kernel<false, false, EpiAtomPlain>, cudaFuncAttributeMaxDynamicSharedMemorySize, SMEM_BYTES);

    // 0) prep
    prep_kernel<<<2048, 256>>>(mask, out + 4194304);

    // 1) q & vv projections (shared A=v): M=16384 K=256 N=2048, z in {0,1}
    dual_kernel<<<dim3(16, 128, 2), 256, SMEM_BYTES>>>(
        DualP{v, Wv, Wvv, bv, bvv, nullptr, pq, pvv, 0.0625f, 1.0f, 256, 256, 2048, 8192});

    // 2) k & vl projections (shared A=l): M=512 K=768 N=2048, z in {0,1}; vl masked
    dual_kernel<<<dim3(16, 4, 2), 256, SMEM_BYTES>>>(
        DualP{l, Wl, Wvl, bl, bvl, pm, pk, pvl, 1.0f, 1.0f, 768, 768, 2048, 256});

    // 3) W = exp(clip(q k^T)) + row/col sums. per-(b,h): M=8192 N=256 K=256
    attn_kernel<<<dim3(2, 64, 16), 256, SMEM_BYTES>>>(pq, pk, pW, pm, prz, pcz);

    // 4) out_v' = (W @ vl_masked)/rowZ
    gemm_kernel<false, false, EpiOutV><<<dim3(2, 64, 16), 256, SMEM_BYTES>>>(
        GemmP{pW, pvl, 256, 256, 256, 8192L * 256, 256L * 256, 1},
        EpiOutV{prz, pov1});

    // 5) out_v = out_v' @ Wov + bov -> d_out
    gemm_kernel<false, false, EpiBias><<<dim3(2, 128, 1), 256, SMEM_BYTES>>>(
        GemmP{pov1, Wov, 2048, 2048, 256, 0, 0, 1},
        EpiBias{bov, out, 256});

    // 6) out_l'_acc += W^T @ vv   (split-K x8, atomic accumulate)
    gemm_kernel<true, false, EpiAtomL><<<dim3(2, 2, 16 * 8), 256, SMEM_BYTES>>>(
        GemmP{pW, pvv, 8192, 256, 256, 8192L * 256, 8192L * 256, 8},
        EpiAtomL{pol1});

    // 7) out_l' /= colZ
    scale_outl1_kernel<<<4096, 256>>>();

    // 8) out_l_acc += out_l' @ Wol  (split-K x8, atomic; region pre-zeroed)
    gemm_kernel<false, false, EpiAtomPlain><<<dim3(6, 4, 8), 256, SMEM_BYTES>>>(
        GemmP{pol1, Wol, 2048, 2048, 768, 0, 0, 8},
        EpiAtomPlain{out + 4194304, 768});

    // 9) out_l += bol
    add_bol_kernel<<<1536, 256>>>(out + 4194304, bol);
}

// round 4
// speedup vs baseline: 1.5051x; 1.5051x over previous
#include <cuda_runtime.h>
#include <cstdint>

#define DEV_INLINE __device__ __forceinline__

// ---------------- problem constants ----------------
// B=2, TV=8192, TL=256, E=2048, H=8, D=256, VD=256, LD=768, scale=0.0625

// ---------------- scratch ----------------
__device__ __align__(16) float g_q   [(size_t)16 * 8192 * 256];   // [b,h,t,d] tf32
__device__ __align__(16) float g_vv  [(size_t)16 * 8192 * 256];   // [b,h,t,d] tf32
__device__ __align__(16) float g_k   [16 * 256 * 256];            // [b,h,s,d] tf32
__device__ __align__(16) float g_vl  [16 * 256 * 256];            // [b,h,s,d] tf32, pre-masked
__device__ __align__(16) float g_W   [(size_t)16 * 8192 * 256];   // exp(clip(attn)) tf32
__device__ __align__(16) float g_outv1[(size_t)2 * 8192 * 2048];  // [b,t,E] tf32
__device__ __align__(16) float g_outl1[2 * 256 * 2048];           // [b,s,E] acc -> tf32
__device__ float g_rowZ[16 * 8192];
__device__ float g_colZ[16 * 256];
__device__ float g_maskf[512];

// ---------------- helpers ----------------
DEV_INLINE uint32_t frag_cvt(const float* p) {
    uint32_t u;
    asm("cvt.rna.tf32.f32 %0, %1;" : "=r"(u) : "f"(*p));
    return u;
}
DEV_INLINE float tf32r(float x) {
    uint32_t u;
    asm("cvt.rna.tf32.f32 %0, %1;" : "=r"(u) : "f"(x));
    return __uint_as_float(u);
}
template<bool CVT>
DEV_INLINE uint32_t fld(const float* p) {
    if (CVT) return frag_cvt(p);
    return __float_as_uint(*p);
}

DEV_INLINE void mma8(float (&c)[4], const uint32_t (&a)[4], const uint32_t (&b)[2]) {
    asm volatile(
        "mma.sync.aligned.m16n8k8.row.col.f32.tf32.tf32.f32 "
        "{%0,%1,%2,%3}, {%4,%5,%6,%7}, {%8,%9}, {%0,%1,%2,%3};\n"
        : "+f"(c[0]), "+f"(c[1]), "+f"(c[2]), "+f"(c[3])
        : "r"(a[0]), "r"(a[1]), "r"(a[2]), "r"(a[3]), "r"(b[0]), "r"(b[1]));
}

DEV_INLINE void cp16(float* dst, const float* src) {
    uint32_t d = (uint32_t)__cvta_generic_to_shared(dst);
    asm volatile("cp.async.cg.shared.global [%0], [%1], 16;\n" :: "r"(d), "l"(src));
}
DEV_INLINE void cpcommit() { asm volatile("cp.async.commit_group;\n"); }
DEV_INLINE void cpwait1()  { asm volatile("cp.async.wait_group 1;\n"); }

// ---------------- unified GEMM core ----------------
// NB=128: warps 2x4, warp tile 64x32, acc[4][4][4]  (for LDS-bound big tiles)
// NB=64 : warps 4x2, warp tile 32x32, acc[2][4][4]  (for grid-starved shapes)
// smem strides: A normal [m][36], A trans [k][136], B KN [k][136|68], B NT [n][36]
constexpr int BM = 128, BK = 32;

constexpr int smem_bytes(int NB, bool ATRANS, bool BNT) {
    int ASZ = ATRANS ? 32 * 136 : 128 * 36;
    int BSZ = BNT ? NB * 36 : 32 * (NB == 128 ? 136 : 68);
    return 2 * (ASZ + BSZ) * 4;
}

template<int NB, bool ATRANS, bool BNT>
DEV_INLINE void load_stage(const float* A, const float* B, int k0,
                           int lda, int ldb, int m0, int n0,
                           float* As, float* Bs, int tid) {
    constexpr int BSTR = (NB == 128 ? 136 : 68);
    if (!ATRANS) {
        #pragma unroll
        for (int i = 0; i < 4; i++) {
            int lin = tid + i * 256;
            int r = lin >> 3, c4 = (lin & 7) << 2;
            cp16(As + r * 36 + c4, A + (size_t)(m0 + r) * lda + k0 + c4);
        }
    } else {
        #pragma unroll
        for (int i = 0; i < 4; i++) {
            int lin = tid + i * 256;
            int kk = lin >> 5, m4 = (lin & 31) << 2;
            cp16(As + kk * 136 + m4, A + (size_t)(k0 + kk) * lda + m0 + m4);
        }
    }
    if (BNT) {
        #pragma unroll
        for (int i = 0; i < NB / 32; i++) {
            int lin = tid + i * 256;
            int r = lin >> 3, c4 = (lin & 7) << 2;
            cp16(Bs + r * 36 + c4, B + (size_t)(n0 + r) * ldb + k0 + c4);
        }
    } else {
        #pragma unroll
        for (int i = 0; i < NB / 32; i++) {
            int lin = tid + i * 256;
            int kk = lin / (NB / 4), n4 = (lin % (NB / 4)) << 2;
            cp16(Bs + kk * BSTR + n4, B + (size_t)(k0 + kk) * ldb + n0 + n4);
        }
    }
}

template<int NB, bool ATRANS, bool BNT, bool CVTA, bool CVTB>
DEV_INLINE void compute_stage(const float* As, const float* Bs,
                              int wm, int wn, int gid, int tig,
                              float (&acc)[NB == 128 ? 4 : 2][4][4]) {
    constexpr int MI = (NB == 128 ? 4 : 2);
    constexpr int BSTR = (NB == 128 ? 136 : 68);
    #pragma unroll
    for (int ks = 0; ks < 4; ks++) {
        const int kb = ks << 3;
        uint32_t a[MI][4], b[4][2];
        #pragma unroll
        for (int im = 0; im < MI; im++) {
            int row = wm + im * 16 + gid;
            if (!ATRANS) {
                a[im][0] = fld<CVTA>(As + row * 36 + kb + tig);
                a[im][1] = fld<CVTA>(As + (row + 8) * 36 + kb + tig);
                a[im][2] = fld<CVTA>(As + row * 36 + kb + tig + 4);
                a[im][3] = fld<CVTA>(As + (row + 8) * 36 + kb + tig + 4);
            } else {
                a[im][0] = fld<CVTA>(As + (kb + tig) * 136 + row);
                a[im][1] = fld<CVTA>(As + (kb + tig) * 136 + row + 8);
                a[im][2] = fld<CVTA>(As + (kb + tig + 4) * 136 + row);
                a[im][3] = fld<CVTA>(As + (kb + tig + 4) * 136 + row + 8);
            }
        }
        #pragma unroll
        for (int jn = 0; jn < 4; jn++) {
            int col = wn + jn * 8 + gid;
            if (BNT) {
                b[jn][0] = fld<CVTB>(Bs + col * 36 + kb + tig);
                b[jn][1] = fld<CVTB>(Bs + col * 36 + kb + tig + 4);
            } else {
                b[jn][0] = fld<CVTB>(Bs + (kb + tig) * BSTR + col);
                b[jn][1] = fld<CVTB>(Bs + (kb + tig + 4) * BSTR + col);
            }
        }
        #pragma unroll
        for (int im = 0; im < MI; im++)
            #pragma unroll
            for (int jn = 0; jn < 4; jn++)
                mma8(acc[im][jn], a[im], b[jn]);
    }
}

template<int NB, bool ATRANS, bool BNT, bool CVTA, bool CVTB>
DEV_INLINE void gemm_core(const float* A, const float* B, int kbeg, int kcnt,
                          int lda, int ldb, int m0, int n0,
                          float (&acc)[NB == 128 ? 4 : 2][4][4]) {
    extern __shared__ float smem[];
    constexpr int MI = (NB == 128 ? 4 : 2);
    constexpr int ASZ = ATRANS ? 32 * 136 : 128 * 36;
    constexpr int BSZ = BNT ? NB * 36 : 32 * (NB == 128 ? 136 : 68);
    float* Asb[2] = { smem, smem + ASZ };
    float* Bsb[2] = { smem + 2 * ASZ, smem + 2 * ASZ + BSZ };

    const int tid = threadIdx.x;
    const int lane = tid & 31, warp = tid >> 5;
    const int wm = (NB == 128) ? (warp >> 2) * 64 : (warp & 3) * 32;
    const int wn = (NB == 128) ? (warp & 3) * 32 : (warp >> 2) * 32;
    const int gid = lane >> 2, tig = lane & 3;

    #pragma unroll
    for (int i = 0; i < MI; i++)
        #pragma unroll
        for (int j = 0; j < 4; j++)
            #pragma unroll
            for (int q = 0; q < 4; q++) acc[i][j][q] = 0.f;

    const int nk = kcnt >> 5;
    load_stage<NB, ATRANS, BNT>(A, B, kbeg, lda, ldb, m0, n0, Asb[0], Bsb[0], tid);
    cpcommit();
    for (int i = 0; i < nk; i++) {
        if (i + 1 < nk)
            load_stage<NB, ATRANS, BNT>(A, B, kbeg + ((i + 1) << 5), lda, ldb, m0, n0,
                                        Asb[(i + 1) & 1], Bsb[(i + 1) & 1], tid);
        cpcommit();
        cpwait1();
        __syncthreads();
        compute_stage<NB, ATRANS, BNT, CVTA, CVTB>(Asb[i & 1], Bsb[i & 1], wm, wn, gid, tig, acc);
        __syncthreads();
    }
}

// ---------------- generic GEMM kernel ----------------
struct GemmP {
    const float* A; const float* B;
    int K, lda, ldb;
    long aB, bB;
    int ksplit;
};

template<int NB, bool ATRANS, bool BNT, bool CVTA, bool CVTB, class Epi>
__global__ __launch_bounds__(256, 2) void gemm_kernel(GemmP p, Epi epi) {
    constexpr int MI = (NB == 128 ? 4 : 2);
    const int zz = blockIdx.z;
    const int z  = (p.ksplit > 1) ? zz / p.ksplit : zz;
    const int sp = (p.ksplit > 1) ? zz % p.ksplit : 0;
    const int kcnt = p.K / p.ksplit;
    const int kbeg = sp * kcnt;
    const float* A = p.A + (size_t)z * p.aB;
    const float* B = p.B + (size_t)z * p.bB;
    const int m0 = blockIdx.y * BM, n0 = blockIdx.x * NB;

    float acc[MI][4][4];
    gemm_core<NB, ATRANS, BNT, CVTA, CVTB>(A, B, kbeg, kcnt, p.lda, p.ldb, m0, n0, acc);

    const int lane = threadIdx.x & 31, warp = threadIdx.x >> 5;
    const int wm = (NB == 128) ? (warp >> 2) * 64 : (warp & 3) * 32;
    const int wn = (NB == 128) ? (warp & 3) * 32 : (warp >> 2) * 32;
    const int gid = lane >> 2, tig = lane & 3;
    #pragma unroll
    for (int im = 0; im < MI; im++)
        #pragma unroll
        for (int jn = 0; jn < 4; jn++)
            #pragma unroll
            for (int qd = 0; qd < 4; qd++) {
                int r = m0 + wm + im * 16 + gid + ((qd >> 1) << 3);
                int c = n0 + wn + jn * 8 + tig * 2 + (qd & 1);
                epi(z, r, c, acc[im][jn][qd]);
            }
}

// ---------------- dual-projection kernel (shared A, z picks weights) ----------------
struct DualP {
    const float* A;
    const float* B0; const float* B1;
    const float* bias0; const float* bias1;
    const float* mask;          // applied when z==1 (vl)
    float* out0; float* out1;
    float a0, a1;
    int K, lda, ldb, T;
};

template<int NB>
__global__ __launch_bounds__(256, 2) void dual_kernel(DualP p) {
    constexpr int MI = (NB == 128 ? 4 : 2);
    const int z = blockIdx.z;
    const float* B = z ? p.B1 : p.B0;
    const int m0 = blockIdx.y * BM, n0 = blockIdx.x * NB;

    float acc[MI][4][4];
    gemm_core<NB, false, false, true, true>(p.A, B, 0, p.K, p.lda, p.ldb, m0, n0, acc);

    const float* bias = z ? p.bias1 : p.bias0;
    float* out = z ? p.out1 : p.out0;
    const float alpha = z ? p.a1 : p.a0;
    const bool useMask = (p.mask != nullptr) && (z == 1);

    const int lane = threadIdx.x & 31, warp = threadIdx.x >> 5;
    const int wm = (NB == 128) ? (warp >> 2) * 64 : (warp & 3) * 32;
    const int wn = (NB == 128) ? (warp & 3) * 32 : (warp >> 2) * 32;
    const int gid = lane >> 2, tig = lane & 3;
    #pragma unroll
    for (int im = 0; im < MI; im++)
        #pragma unroll
        for (int jn = 0; jn < 4; jn++)
            #pragma unroll
            for (int qd = 0; qd < 4; qd++) {
                int r = m0 + wm + im * 16 + gid + ((qd >> 1) << 3);
                int c = n0 + wn + jn * 8 + tig * 2 + (qd & 1);
                float x = (acc[im][jn][qd] + bias[c]) * alpha;
                if (useMask) x *= p.mask[r];
                int b = r / p.T, t = r - b * p.T;
                int h = c >> 8, d = c & 255;
                out[(((size_t)(b * 8 + h)) * p.T + t) * 256 + d] = tf32r(x);
            }
}

// ---------------- epilogues ----------------
struct EpiOutV {
    const float* rowZ; float* out;
    DEV_INLINE void operator()(int z, int r, int c, float v) const {
        int b = z >> 3, h = z & 7;
        out[((size_t)b * 8192 + r) * 2048 + h * 256 + c] = tf32r(v / rowZ[z * 8192 + r]);
    }
};
struct EpiBias {
    const float* bias; float* out; int ldc;
    DEV_INLINE void operator()(int, int r, int c, float v) const {
        out[(size_t)r * ldc + c] = v + bias[c];
    }
};
struct EpiAtomL {
    float* out;
    DEV_INLINE void operator()(int z, int r, int c, float v) const {
        int b = z >> 3, h = z & 7;
        atomicAdd(&out[((size_t)b * 256 + r) * 2048 + h * 256 + c], v);
    }
};
struct EpiAtomPlain {
    float* out; int ldc;
    DEV_INLINE void operator()(int, int r, int c, float v) const {
        atomicAdd(&out[(size_t)r * ldc + c], v);
    }
};

// ---------------- attention kernel (NB=128 geometry, no-cvt frags) ----------------
__global__ __launch_bounds__(256, 2) void attn_kernel(
    const float* __restrict__ q, const float* __restrict__ kmat,
    float* __restrict__ W, const float* __restrict__ maskf,
    float* __restrict__ rowZ, float* __restrict__ colZ) {
    __shared__ float s_row[128];
    __shared__ float s_col[128];
    __shared__ float s_mask[128];

    const int z = blockIdx.z;
    const float* A = q    + (size_t)z * (8192 * 256);
    const float* B = kmat + (size_t)z * (256 * 256);
    const int m0 = blockIdx.y * BM, n0 = blockIdx.x * 128;
    const int tid = threadIdx.x;

    if (tid < 128) {
        s_row[tid] = 0.f;
        s_col[tid] = 0.f;
        s_mask[tid] = maskf[(z >> 3) * 256 + n0 + tid];
    }
    // core's internal __syncthreads orders these before the epilogue

    float acc[4][4][4];
    gemm_core<128, false, true, false, false>(A, B, 0, 256, 256, 256, m0, n0, acc);

    const int lane = tid & 31, warp = tid >> 5;
    const int wm = (warp >> 2) * 64, wn = (warp & 3) * 32;
    const int gid = lane >> 2, tig = lane & 3;
    const size_t wbase = (size_t)z * (8192 * 256);

    float colp[4][2] = {};   // [jn][q&1]
    float rowp[4][2] = {};   // [im][q>>1]

    #pragma unroll
    for (int im = 0; im < 4; im++)
        #pragma unroll
        for (int jn = 0; jn < 4; jn++)
            #pragma unroll
            for (int qd = 0; qd < 4; qd++) {
                int rr = wm + im * 16 + gid + ((qd >> 1) << 3);
                int cc = wn + jn * 8 + tig * 2 + (qd & 1);
                float x = fminf(fmaxf(acc[im][jn][qd], -50000.f), 50000.f);
                float w = __expf(x);
                W[wbase + (size_t)(m0 + rr) * 256 + (n0 + cc)] = tf32r(w);
                colp[jn][qd & 1] += w;
                rowp[im][qd >> 1] += w * s_mask[cc];
            }

    #pragma unroll
    for (int jn = 0; jn < 4; jn++)
        #pragma unroll
        for (int q1 = 0; q1 < 2; q1++) {
            float v = colp[jn][q1];
            v += __shfl_xor_sync(0xffffffffu, v, 4);
            v += __shfl_xor_sync(0xffffffffu, v, 8);
            v += __shfl_xor_sync(0xffffffffu, v, 16);
            if (gid == 0) atomicAdd(&s_col[wn + jn * 8 + tig * 2 + q1], v);
        }
    #pragma unroll
    for (int im = 0; im < 4; im++)
        #pragma unroll
        for (int qh = 0; qh < 2; qh++) {
            float v = rowp[im][qh];
            v += __shfl_xor_sync(0xffffffffu, v, 1);
            v += __shfl_xor_sync(0xffffffffu, v, 2);
            if (tig == 0) atomicAdd(&s_row[wm + im * 16 + gid + qh * 8], v);
        }

    __syncthreads();
    if (tid < 128) {
        atomicAdd(&rowZ[z * 8192 + m0 + tid], s_row[tid]);
        atomicAdd(&colZ[z * 256 + n0 + tid], s_col[tid]);
    }
}

// ---------------- small kernels ----------------
__global__ void prep_kernel(const int* __restrict__ mask, float* __restrict__ outl_region) {
    int i = blockIdx.x * 256 + threadIdx.x;
    int n = gridDim.x * 256;
    for (int j = i; j < 2 * 256 * 2048; j += n) g_outl1[j] = 0.f;
    for (int j = i; j < 512 * 768;      j += n) outl_region[j] = 0.f;
    for (int j = i; j < 16 * 8192;      j += n) g_rowZ[j] = 0.f;
    for (int j = i; j < 16 * 256;       j += n) g_colZ[j] = 0.f;
    for (int j = i; j < 512;            j += n) g_maskf[j] = (float)mask[j];
}

__global__ void scale_outl1_kernel() {
    int i = blockIdx.x * 256 + threadIdx.x;   // total 2*256*2048
    int b = i / (256 * 2048);
    int rem = i - b * (256 * 2048);
    int s = rem >> 11;
    int h = (rem >> 8) & 7;
    g_outl1[i] = tf32r(g_outl1[i] / g_colZ[(b * 8 + h) * 256 + s]);
}

__global__ void add_bol_kernel(float* __restrict__ out, const float* __restrict__ bol) {
    int i = blockIdx.x * 256 + threadIdx.x;   // total 512*768
    if (i < 512 * 768) out[i] += bol[i % 768];
}

// ---------------- host ----------------
extern "C" void kernel_launch(void* const* d_in, const int* in_sizes, int n_in,
                              void* d_out, int out_size) {
    (void)in_sizes; (void)n_in; (void)out_size;
    const float* v    = (const float*)d_in[0];
    const float* l    = (const float*)d_in[1];
    const int*   mask = (const int*)d_in[2];
    const float* Wv   = (const float*)d_in[3];
    const float* bv   = (const float*)d_in[4];
    const float* Wl   = (const float*)d_in[5];
    const float* bl   = (const float*)d_in[6];
    const float* Wvv  = (const float*)d_in[7];
    const float* bvv  = (const float*)d_in[8];
    const float* Wvl  = (const float*)d_in[9];
    const float* bvl  = (const float*)d_in[10];
    const float* Wov  = (const float*)d_in[11];
    const float* bov  = (const float*)d_in[12];
    const float* Wol  = (const float*)d_in[13];
    const float* bol  = (const float*)d_in[14];
    float* out = (float*)d_out;

    float *pq, *pvv, *pk, *pvl, *pW, *pov1, *pol1, *prz, *pcz, *pm;
    cudaGetSymbolAddress((void**)&pq,   g_q);
    cudaGetSymbolAddress((void**)&pvv,  g_vv);
    cudaGetSymbolAddress((void**)&pk,   g_k);
    cudaGetSymbolAddress((void**)&pvl,  g_vl);
    cudaGetSymbolAddress((void**)&pW,   g_W);
    cudaGetSymbolAddress((void**)&pov1, g_outv1);
    cudaGetSymbolAddress((void**)&pol1, g_outl1);
    cudaGetSymbolAddress((void**)&prz,  g_rowZ);
    cudaGetSymbolAddress((void**)&pcz,  g_colZ);
    cudaGetSymbolAddress((void**)&pm,   g_maskf);

    constexpr int SM_D128  = smem_bytes(128, false, false);   // dual big
    constexpr int SM_D64   = smem_bytes(64,  false, false);   // dual small / step5 / step8
    constexpr int SM_ATT   = smem_bytes(128, false, true);    // attn
    constexpr int SM_S4    = smem_bytes(128, false, false);   // step4
    constexpr int SM_S6    = smem_bytes(128, true,  false);   // step6

    cudaFuncSetAttribute(dual_kernel<128>, cudaFuncAttributeMaxDynamicSharedMemorySize, SM_D128);
    cudaFuncSetAttribute(dual_kernel<64>,  cudaFuncAttributeMaxDynamicSharedMemorySize, SM_D64);
    cudaFuncSetAttribute(attn_kernel,      cudaFuncAttributeMaxDynamicSharedMemorySize, SM_ATT);
    cudaFuncSetAttribute(gemm_kernel<128, false, false, false, false, EpiOutV>,
                         cudaFuncAttributeMaxDynamicSharedMemorySize, SM_S4);
    cudaFuncSetAttribute(gemm_kernel<64, false, false, false, true, EpiBias>,
                         cudaFuncAttributeMaxDynamicSharedMemorySize, SM_D64);
    cudaFuncSetAttribute(gemm_kernel<128, true, false, false, false, EpiAtomL>,
                         cudaFuncAttributeMaxDynamicSharedMemorySize, SM_S6);
    cudaFuncSetAttribute(gemm_kernel<64, false, false, false, true, EpiAtomPlain>,
                         cudaFuncAttributeMaxDynamicSharedMemorySize, SM_D64);

    // 0) prep
    prep_kernel<<<512, 256>>>(mask, out + 4194304);

    // 1) q & vv projections (shared A=v): M=16384 K=256 N=2048
    dual_kernel<128><<<dim3(16, 128, 2), 256, SM_D128>>>(
        DualP{v, Wv, Wvv, bv, bvv, nullptr, pq, pvv, 0.0625f, 1.0f, 256, 256, 2048, 8192});

    // 2) k & vl projections (shared A=l): M=512 K=768 N=2048 (NB=64 -> 256 blocks)
    dual_kernel<64><<<dim3(32, 4, 2), 256, SM_D64>>>(
        DualP{l, Wl, Wvl, bl, bvl, pm, pk, pvl, 1.0f, 1.0f, 768, 768, 2048, 256});

    // 3) W = exp(clip(q k^T)) + row/col sums. per-(b,h): M=8192 N=256 K=256
    attn_kernel<<<dim3(2, 64, 16), 256, SM_ATT>>>(pq, pk, pW, pm, prz, pcz);

    // 4) out_v' = (W @ vl_masked)/rowZ  (tf32-rounded store)
    gemm_kernel<128, false, false, false, false, EpiOutV><<<dim3(2, 64, 16), 256, SM_S4>>>(
        GemmP{pW, pvl, 256, 256, 256, 8192L * 256, 256L * 256, 1},
        EpiOutV{prz, pov1});

    // 5) out_v = out_v' @ Wov + bov -> d_out  (NB=64 -> 512 blocks)
    gemm_kernel<64, false, false, false, true, EpiBias><<<dim3(4, 128, 1), 256, SM_D64>>>(
        GemmP{pov1, Wov, 2048, 2048, 256, 0, 0, 1},
        EpiBias{bov, out, 256});

    // 6) out_l'_acc += W^T @ vv   (split-K x8, atomic accumulate)
    gemm_kernel<128, true, false, false, false, EpiAtomL><<<dim3(2, 2, 16 * 8), 256, SM_S6>>>(
        GemmP{pW, pvv, 8192, 256, 256, 8192L * 256, 8192L * 256, 8},
        EpiAtomL{pol1});

    // 7) out_l' /= colZ (tf32-rounded)
    scale_outl1_kernel<<<4096, 256>>>();

    // 8) out_l_acc += out_l' @ Wol  (split-K x8; NB=64 -> 384 blocks)
    gemm_kernel<64, false, false, false, true, EpiAtomPlain><<<dim3(12, 4, 8), 256, SM_D64>>>(
        GemmP{pol1, Wol, 2048, 2048, 768, 0, 0, 8},
        EpiAtomPlain{out + 4194304, 768});

    // 9) out_l += bol
    add_bol_kernel<<<1536, 256>>>(out + 4194304, bol);
}